// round 7
// baseline (speedup 1.0000x reference)
#include <cuda_runtime.h>
#include <cuda_bf16.h>

#define NC 50000
#define BATCH 128
#define ROWS 768                 // 6 parts * 128
#define DIM 1536                 // 6 * 256
#define N4 12500                 // float4 per row
#define KTILE 128
#define NTILE (DIM / KTILE)      // 12
#define NDIST 128                // dist blocks (bid 0..127)
#define NBLK (NDIST + ROWS)      // 896 total blocks

// ---------------- device scratch (no cudaMalloc allowed) ----------------
__device__ float g_ce[ROWS];            // ce + 0.1*adv_nll per row
__device__ float g_klw[ROWS];
__device__ float g_tri[2 * BATCH];
__device__ float g_F[BATCH * DIM];      // normalized feat rows, fp32
__device__ __align__(16) __nv_bfloat16 g_TtB[DIM * 256]; // transposed targets
__device__ float g_n2[256];
__device__ unsigned g_cnt;              // last-block counter (self-resetting)

__device__ __forceinline__ float ex2(float v) {
    float r;
    asm("ex2.approx.ftz.f32 %0, %1;" : "=f"(r) : "f"(v));
    return r;
}
__device__ __forceinline__ void cpa16(unsigned dst, const void* src) {
    asm volatile("cp.async.ca.shared.global [%0], [%1], 16;" :: "r"(dst), "l"(src));
}

// ============================================================
// prep: normalize concatenated part features; fp32 rows + bf16 transpose.
// ============================================================
__global__ __launch_bounds__(256) void prep_kernel(
    const float* __restrict__ idf, const float* __restrict__ gf)
{
    const int tid = threadIdx.x;
    const int lane = tid & 31, wid = tid >> 5;
    const unsigned full = 0xffffffffu;

    int j = blockIdx.x;                 // 0..255
    const float* src = (j < BATCH) ? idf : gf;
    int b = j & (BATCH - 1);

    float v[6];
    float sq = 0.f;
#pragma unroll
    for (int p = 0; p < 6; p++) {
        float x = src[(size_t)(p * BATCH + b) * 256 + tid];
        v[p] = x;
        sq = fmaf(x, x, sq);
    }
#pragma unroll
    for (int off = 16; off; off >>= 1) sq += __shfl_down_sync(full, sq, off);
    __shared__ float wsum[8];
    if (lane == 0) wsum[wid] = sq;
    __syncthreads();
    float tot = 0.f;
#pragma unroll
    for (int w = 0; w < 8; w++) tot += wsum[w];
    float rn = rsqrtf(tot);
#pragma unroll
    for (int p = 0; p < 6; p++) {
        int d = p * 256 + tid;
        float nv = v[p] * rn;
        g_TtB[(size_t)d * 256 + j] = __float2bfloat16_rn(nv);
        if (j < BATCH) g_F[(size_t)b * DIM + d] = nv;
    }
    if (tid == 0) g_n2[j] = tot * rn * rn;
}

// ============================================================
// mega: bid 0..127 dist path (cp.async 2-stage pipelined GEMM + mining);
//       bid 128..895 row path (dual-temp softmax stats, HBM-bound).
// Heterogeneous blocks in ONE grid -> hardware-guaranteed overlap.
// Last finished block performs the final scalar reduce.
// ============================================================
struct __align__(16) MegaSmem {
    union {
        struct {
            __nv_bfloat16 Ts[2][KTILE][128];   // 64 KB
            float As[2][2][KTILE];             // 2 KB
            float red[8][2][128];              // 8 KB
            float wmax[2][8], wmin[2][8];
        } d;
        float sm[6][8];
    } u;
    float fm[4][8];
    int   last;
};

__global__ __launch_bounds__(256, 3) void mega_kernel(
    const float* __restrict__ logits, const float* __restrict__ soft,
    const float* __restrict__ ew,     const int*   __restrict__ labels,
    const float* __restrict__ adv,    const int*   __restrict__ mod,
    const int*   __restrict__ epoch_p, float* __restrict__ out)
{
    __shared__ MegaSmem s;
    const int tid = threadIdx.x;
    const int lane = tid & 31, wid = tid >> 5;
    const unsigned full = 0xffffffffu;

    if (blockIdx.x < NDIST) {
        // ==================== dist path ====================
        int p  = blockIdx.x >> 1;
        int h  = blockIdx.x & 1;
        int i0 = p * 2;

        unsigned ts_base = (unsigned)__cvta_generic_to_shared(s.u.d.Ts);
        unsigned as_base = (unsigned)__cvta_generic_to_shared(s.u.d.As);

        const int trow = tid >> 1;
        const int tcol = (tid & 1) * 128;

        auto stage = [&](int t) {
            int k0 = t * KTILE;
            int st = t & 1;
            const char* gsrc = (const char*)g_TtB
                             + (size_t)(k0 + trow) * 512 + h * 256 + tcol;
            unsigned sdst = ts_base + st * (KTILE * 256) + trow * 256 + tcol;
#pragma unroll
            for (int c8 = 0; c8 < 8; c8++)
                cpa16(sdst + c8 * 16, gsrc + c8 * 16);
            if (tid < 64) {
                int a  = tid >> 5;
                int ch = tid & 31;
                const char* asrc = (const char*)(g_F + (size_t)(i0 + a) * DIM + k0)
                                 + ch * 16;
                cpa16(as_base + (st * 2 + a) * (KTILE * 4) + ch * 16, asrc);
            }
            asm volatile("cp.async.commit_group;");
        };

        float c00 = 0.f, c01 = 0.f, c02 = 0.f, c03 = 0.f;
        float c10 = 0.f, c11 = 0.f, c12 = 0.f, c13 = 0.f;

        stage(0);
#pragma unroll 1
        for (int t = 0; t < NTILE; t++) {
            if (t + 1 < NTILE) {
                stage(t + 1);
                asm volatile("cp.async.wait_group 1;" ::: "memory");
            } else {
                asm volatile("cp.async.wait_group 0;" ::: "memory");
            }
            __syncthreads();

            int st = t & 1;
            int kl0 = wid * 16;
#pragma unroll
            for (int kk = 0; kk < 16; kk++) {
                int k = kl0 + kk;
                uint2 tv = *(const uint2*)((const char*)s.u.d.Ts[st] + k * 256 + lane * 8);
                float f0 = __uint_as_float(tv.x << 16);
                float f1 = __uint_as_float(tv.x & 0xffff0000u);
                float f2 = __uint_as_float(tv.y << 16);
                float f3 = __uint_as_float(tv.y & 0xffff0000u);
                float A0 = s.u.d.As[st][0][k], A1 = s.u.d.As[st][1][k];
                c00 = fmaf(A0, f0, c00); c01 = fmaf(A0, f1, c01);
                c02 = fmaf(A0, f2, c02); c03 = fmaf(A0, f3, c03);
                c10 = fmaf(A1, f0, c10); c11 = fmaf(A1, f1, c11);
                c12 = fmaf(A1, f2, c12); c13 = fmaf(A1, f3, c13);
            }
            __syncthreads();
        }

        ((float4*)s.u.d.red[wid][0])[lane] = make_float4(c00, c01, c02, c03);
        ((float4*)s.u.d.red[wid][1])[lane] = make_float4(c10, c11, c12, c13);
        __syncthreads();

        int a  = tid >> 7;
        int jl = tid & 127;
        int ia = i0 + a;
        int jglob = h * 128 + jl;

        float dot = 0.f;
#pragma unroll
        for (int sl = 0; sl < 8; sl++) dot += s.u.d.red[sl][a][jl];
        float sqv = g_n2[ia] + g_n2[jglob] - 2.f * dot;
        float dj  = sqrtf(fmaxf(sqv, 0.f) + 1e-12f);

        bool eq  = (labels[ia] == labels[jl]);
        bool pos = h ? eq : (eq && (jl != ia));
        float apv = pos   ? dj : -1e30f;
        float anv = (!eq) ? dj :  1e30f;
#pragma unroll
        for (int off = 16; off; off >>= 1) {
            apv = fmaxf(apv, __shfl_down_sync(full, apv, off));
            anv = fminf(anv, __shfl_down_sync(full, anv, off));
        }
        if (lane == 0) { s.u.d.wmax[a][wid & 3] = apv; s.u.d.wmin[a][wid & 3] = anv; }
        __syncthreads();

        if ((tid & 127) == 0) {
            float apm = fmaxf(fmaxf(s.u.d.wmax[a][0], s.u.d.wmax[a][1]),
                              fmaxf(s.u.d.wmax[a][2], s.u.d.wmax[a][3]));
            float anm = fminf(fminf(s.u.d.wmin[a][0], s.u.d.wmin[a][1]),
                              fminf(s.u.d.wmin[a][2], s.u.d.wmin[a][3]));
            float dap = (apm > -1e29f) ? apm : 0.f;
            float dan = (anm <  1e29f) ? anm : 1e6f;
            g_tri[h * BATCH + ia] = fmaxf(dap - dan + 0.3f, 0.f);
            __threadfence();
        }
    } else {
        // ==================== row path ====================
        const int r = blockIdx.x - NDIST;
        const float4* lg4 = (const float4*)(logits + (size_t)r * NC);
        const float4* sf4 = (const float4*)(soft   + (size_t)r * NC);
        const float C = 0.48089834696298783f;   // log2(e)/3

        float4 vs1 = {0,0,0,0}, vs2 = {0,0,0,0}, vsx = {0,0,0,0};
        float4 vss = {0,0,0,0}, vssx = {0,0,0,0}, vssl = {0,0,0,0};

#define ACC(xx, sv_, L)                                               \
    {   float x = xx, sv = sv_;                                       \
        vsx.L += x;  vss.L += sv;                                     \
        vssx.L = fmaf(sv, x, vssx.L);                                 \
        vssl.L = fmaf(sv, __log2f(fmaxf(sv, 1e-38f)), vssl.L);        \
        float e = ex2(x * C);                                         \
        vs2.L += e;                                                   \
        vs1.L = fmaf(e * e, e, vs1.L); }
#define LANE4(x4, t4) ACC(x4.x, t4.x, x) ACC(x4.y, t4.y, y) \
                      ACC(x4.z, t4.z, z) ACC(x4.w, t4.w, w)

        int i = tid;
        for (; i + 768 < N4; i += 1024) {
            float4 x0 = __ldcs(lg4 + i);
            float4 x1 = __ldcs(lg4 + i + 256);
            float4 x2 = __ldcs(lg4 + i + 512);
            float4 x3 = __ldcs(lg4 + i + 768);
            float4 t0 = __ldcs(sf4 + i);
            float4 t1 = __ldcs(sf4 + i + 256);
            float4 t2 = __ldcs(sf4 + i + 512);
            float4 t3 = __ldcs(sf4 + i + 768);
            LANE4(x0, t0) LANE4(x1, t1) LANE4(x2, t2) LANE4(x3, t3)
        }
        for (; i < N4; i += 256) {
            float4 x0 = __ldcs(lg4 + i);
            float4 t0 = __ldcs(sf4 + i);
            LANE4(x0, t0)
        }
#undef LANE4
#undef ACC

        float s1  = (vs1.x + vs1.y) + (vs1.z + vs1.w);
        float s2  = (vs2.x + vs2.y) + (vs2.z + vs2.w);
        float sx  = (vsx.x + vsx.y) + (vsx.z + vsx.w);
        float ssv = (vss.x + vss.y) + (vss.z + vss.w);
        float ssx = (vssx.x + vssx.y) + (vssx.z + vssx.w);
        float ssl = (vssl.x + vssl.y) + (vssl.z + vssl.w);

#pragma unroll
        for (int off = 16; off; off >>= 1) {
            s1  += __shfl_down_sync(full, s1,  off);
            s2  += __shfl_down_sync(full, s2,  off);
            sx  += __shfl_down_sync(full, sx,  off);
            ssv += __shfl_down_sync(full, ssv, off);
            ssx += __shfl_down_sync(full, ssx, off);
            ssl += __shfl_down_sync(full, ssl, off);
        }

        if (lane == 0) {
            s.u.sm[0][wid] = s1;  s.u.sm[1][wid] = s2;  s.u.sm[2][wid] = sx;
            s.u.sm[3][wid] = ssv; s.u.sm[4][wid] = ssx; s.u.sm[5][wid] = ssl;
        }
        __syncthreads();

        if (tid == 0) {
            s1 = 0.f; s2 = 0.f; sx = 0.f; ssv = 0.f; ssx = 0.f; ssl = 0.f;
#pragma unroll
            for (int w = 0; w < 8; w++) {
                s1 += s.u.sm[0][w]; s2 += s.u.sm[1][w]; sx += s.u.sm[2][w];
                ssv += s.u.sm[3][w]; ssx += s.u.sm[4][w]; ssl += s.u.sm[5][w];
            }
            float logZ1 = __logf(s1);
            float logZ2 = __logf(s2);

            int   b   = r & (BATCH - 1);
            int   lab = labels[b];
            float xl  = logits[(size_t)r * NC + lab];
            float ce  = logZ1 - 0.9f * xl - 0.1f * sx * (1.f / (float)NC);

            float l0 = adv[2 * r], l1 = adv[2 * r + 1];
            float mm = fmaxf(l0, l1);
            float lse = mm + __logf(__expf(l0 - mm) + __expf(l1 - mm));
            float anll = lse - (mod[b] ? l1 : l0);
            g_ce[r] = ce + 0.1f * anll;

            float kl = ssl * 0.6931471805599453f - ssx * (1.f / 3.f) + logZ2 * ssv;
            g_klw[r] = fminf(kl, 5.0f) * ew[r];
            __threadfence();
        }
    }

    // ================= last-block-done final reduce =================
    __syncthreads();
    if (tid == 0) {
        unsigned v = atomicAdd(&g_cnt, 1u);
        s.last = (v == (unsigned)(NBLK - 1));
    }
    __syncthreads();
    if (!s.last) return;
    if (tid == 0) { g_cnt = 0; __threadfence(); }

    float ceA = 0.f, klwA = 0.f, tri0 = 0.f, tri1 = 0.f;
    for (int r = tid; r < ROWS; r += 256) {
        ceA  += g_ce[r];
        klwA += g_klw[r];
    }
    if (tid < BATCH) { tri0 = g_tri[tid]; tri1 = g_tri[BATCH + tid]; }

#pragma unroll
    for (int off = 16; off; off >>= 1) {
        ceA  += __shfl_down_sync(full, ceA,  off);
        klwA += __shfl_down_sync(full, klwA, off);
        tri0 += __shfl_down_sync(full, tri0, off);
        tri1 += __shfl_down_sync(full, tri1, off);
    }
    if (lane == 0) {
        s.fm[0][wid] = ceA; s.fm[1][wid] = klwA;
        s.fm[2][wid] = tri0; s.fm[3][wid] = tri1;
    }
    __syncthreads();

    if (tid == 0) {
        float ceT = 0.f, klwT = 0.f, t0 = 0.f, t1 = 0.f;
#pragma unroll
        for (int w = 0; w < 8; w++) {
            ceT += s.fm[0][w]; klwT += s.fm[1][w];
            t0  += s.fm[2][w]; t1   += s.fm[3][w];
        }
        float L_idadv = ceT * (1.f / (float)ROWS);   // includes 0.1*L_adv
        float L_tri   = (t0 + 0.5f * t1) * (1.f / (float)BATCH);
        float L_graph = (epoch_p[0] >= 20) ? klwT * (9.f / (float)ROWS) : 0.f;
        out[0] = L_idadv + L_tri + 0.1f * L_graph;
    }
}

// ============================================================
extern "C" void kernel_launch(void* const* d_in, const int* in_sizes, int n_in,
                              void* d_out, int out_size)
{
    const float* id_logits     = (const float*)d_in[0];
    const float* id_features   = (const float*)d_in[1];
    const float* gray_features = (const float*)d_in[2];
    const float* soft_labels   = (const float*)d_in[3];
    const float* entropy_w     = (const float*)d_in[4];
    const float* adv_logits    = (const float*)d_in[5];
    const int*   labels        = (const int*)d_in[6];
    const int*   mod_labels    = (const int*)d_in[7];
    const int*   epoch         = (const int*)d_in[8];

    prep_kernel<<<256, 256>>>(id_features, gray_features);
    mega_kernel<<<NBLK, 256>>>(id_logits, soft_labels, entropy_w, labels,
                               adv_logits, mod_labels,
                               epoch, (float*)d_out);
}

// round 8
// speedup vs baseline: 1.3064x; 1.3064x over previous
#include <cuda_runtime.h>
#include <cuda_bf16.h>

#define NC 50000
#define BATCH 128
#define ROWS 768                 // 6 parts * 128
#define DIM 1536                 // 6 * 256
#define N4 12500                 // float4 per row
#define KQ 384                   // K per dist1 block (DIM/4)

// ---------------- device scratch (no cudaMalloc allowed) ----------------
__device__ float g_ce[ROWS];            // ce + 0.1*adv_nll per row
__device__ float g_klw[ROWS];
__device__ float g_tri[2 * BATCH];
__device__ float g_F[BATCH * DIM];      // normalized feat rows, fp32
__device__ __align__(16) __nv_bfloat16 g_TtB[DIM * 256]; // transposed targets
__device__ float g_n2[256];
__device__ float g_dotp[64 * 2 * 4 * 2 * 128]; // [pair][half][quarter][anchor][jl]
__device__ unsigned g_cnt;              // last-block counter (self-resetting)

__device__ __forceinline__ float ex2(float v) {
    float r;
    asm("ex2.approx.ftz.f32 %0, %1;" : "=f"(r) : "f"(v));
    return r;
}

// ============================================================
// prep: normalize concatenated part features; fp32 rows + bf16 transpose.
// ============================================================
__global__ __launch_bounds__(256) void prep_kernel(
    const float* __restrict__ idf, const float* __restrict__ gf)
{
    const int tid = threadIdx.x;
    const int lane = tid & 31, wid = tid >> 5;
    const unsigned full = 0xffffffffu;

    int j = blockIdx.x;                 // 0..255
    const float* src = (j < BATCH) ? idf : gf;
    int b = j & (BATCH - 1);

    float v[6];
    float sq = 0.f;
#pragma unroll
    for (int p = 0; p < 6; p++) {
        float x = src[(size_t)(p * BATCH + b) * 256 + tid];
        v[p] = x;
        sq = fmaf(x, x, sq);
    }
#pragma unroll
    for (int off = 16; off; off >>= 1) sq += __shfl_down_sync(full, sq, off);
    __shared__ float wsum[8];
    if (lane == 0) wsum[wid] = sq;
    __syncthreads();
    float tot = 0.f;
#pragma unroll
    for (int w = 0; w < 8; w++) tot += wsum[w];
    float rn = rsqrtf(tot);
#pragma unroll
    for (int p = 0; p < 6; p++) {
        int d = p * 256 + tid;
        float nv = v[p] * rn;
        g_TtB[(size_t)d * 256 + j] = __float2bfloat16_rn(nv);
        if (j < BATCH) g_F[(size_t)b * DIM + d] = nv;
    }
    if (tid == 0) g_n2[j] = tot * rn * rn;
}

// ============================================================
// dist1: 512 blocks = (64 pairs) x (2 halves) x (4 K-quarters).
// Each block: partial dots of 2 anchors vs 128 targets over 384 k.
// ~3.5 blocks/SM -> ~28 warps/SM: latency actually hidden.
// ============================================================
__global__ __launch_bounds__(256) void dist1_kernel()
{
    __shared__ float As[2][KQ];          // 3 KB
    __shared__ float red[8][2][128];     // 8 KB

    const int tid = threadIdx.x;
    const int lane = tid & 31, wid = tid >> 5;

    int p = blockIdx.x >> 3;
    int h = (blockIdx.x >> 2) & 1;
    int q = blockIdx.x & 3;
    int i0 = p * 2;
    int k0 = q * KQ;

    // load anchor segments: 2 x 384 floats = 3 per thread
#pragma unroll
    for (int u = 0; u < 3; u++) {
        int idx = tid + u * 256;        // 0..767
        int a  = idx >= KQ;
        int kk = a ? idx - KQ : idx;
        As[a][kk] = g_F[(size_t)(i0 + a) * DIM + k0 + kk];
    }
    __syncthreads();

    // slice = warp (48 k each); lane -> 4 targets (uint2 of bf16)
    const uint2* T2 = (const uint2*)g_TtB;
    const int ks = wid * 48;
    const uint2* Tp = T2 + (size_t)(k0 + ks) * 64 + (h * 32 + lane);

    float c00 = 0.f, c01 = 0.f, c02 = 0.f, c03 = 0.f;
    float c10 = 0.f, c11 = 0.f, c12 = 0.f, c13 = 0.f;

#pragma unroll 1
    for (int kk = 0; kk < 48; kk += 8) {
        uint2 t[8];
#pragma unroll
        for (int u = 0; u < 8; u++) t[u] = Tp[(size_t)(kk + u) * 64];
#pragma unroll
        for (int u = 0; u < 8; u++) {
            float f0 = __uint_as_float(t[u].x << 16);
            float f1 = __uint_as_float(t[u].x & 0xffff0000u);
            float f2 = __uint_as_float(t[u].y << 16);
            float f3 = __uint_as_float(t[u].y & 0xffff0000u);
            float A0 = As[0][ks + kk + u], A1 = As[1][ks + kk + u];
            c00 = fmaf(A0, f0, c00); c01 = fmaf(A0, f1, c01);
            c02 = fmaf(A0, f2, c02); c03 = fmaf(A0, f3, c03);
            c10 = fmaf(A1, f0, c10); c11 = fmaf(A1, f1, c11);
            c12 = fmaf(A1, f2, c12); c13 = fmaf(A1, f3, c13);
        }
    }
    ((float4*)red[wid][0])[lane] = make_float4(c00, c01, c02, c03);
    ((float4*)red[wid][1])[lane] = make_float4(c10, c11, c12, c13);
    __syncthreads();

    // combine 8 slices; write partials
    int a  = tid >> 7;
    int jl = tid & 127;
    float dot = 0.f;
#pragma unroll
    for (int sl = 0; sl < 8; sl++) dot += red[sl][a][jl];
    g_dotp[(((size_t)(p * 2 + h) * 4 + q) * 2 + a) * 128 + jl] = dot;
}

// ============================================================
// row: per-row dual-temperature softmax stats; branchless, 8 batched
// LDG.128/iter, per-lane f4 accumulators, reg cap via launch_bounds(256,3).
// ============================================================
__global__ __launch_bounds__(256, 3) void row_kernel(
    const float* __restrict__ logits, const float* __restrict__ soft,
    const float* __restrict__ ew,     const int*   __restrict__ labels,
    const float* __restrict__ adv,    const int*   __restrict__ mod)
{
    const int tid = threadIdx.x;
    const int lane = tid & 31, wid = tid >> 5;
    const unsigned full = 0xffffffffu;

    const int r = blockIdx.x;
    const float4* lg4 = (const float4*)(logits + (size_t)r * NC);
    const float4* sf4 = (const float4*)(soft   + (size_t)r * NC);
    const float C = 0.48089834696298783f;   // log2(e)/3

    float4 vs1 = {0,0,0,0}, vs2 = {0,0,0,0}, vsx = {0,0,0,0};
    float4 vss = {0,0,0,0}, vssx = {0,0,0,0}, vssl = {0,0,0,0};

#define ACC(xx, sv_, L)                                               \
    {   float x = xx, sv = sv_;                                       \
        vsx.L += x;  vss.L += sv;                                     \
        vssx.L = fmaf(sv, x, vssx.L);                                 \
        vssl.L = fmaf(sv, __log2f(fmaxf(sv, 1e-38f)), vssl.L);        \
        float e = ex2(x * C);                                         \
        vs2.L += e;                                                   \
        vs1.L = fmaf(e * e, e, vs1.L); }
#define LANE4(x4, t4) ACC(x4.x, t4.x, x) ACC(x4.y, t4.y, y) \
                      ACC(x4.z, t4.z, z) ACC(x4.w, t4.w, w)

    int i = tid;
    for (; i + 768 < N4; i += 1024) {
        float4 x0 = __ldcs(lg4 + i);
        float4 x1 = __ldcs(lg4 + i + 256);
        float4 x2 = __ldcs(lg4 + i + 512);
        float4 x3 = __ldcs(lg4 + i + 768);
        float4 t0 = __ldcs(sf4 + i);
        float4 t1 = __ldcs(sf4 + i + 256);
        float4 t2 = __ldcs(sf4 + i + 512);
        float4 t3 = __ldcs(sf4 + i + 768);
        LANE4(x0, t0) LANE4(x1, t1) LANE4(x2, t2) LANE4(x3, t3)
    }
    for (; i < N4; i += 256) {
        float4 x0 = __ldcs(lg4 + i);
        float4 t0 = __ldcs(sf4 + i);
        LANE4(x0, t0)
    }
#undef LANE4
#undef ACC

    float s1  = (vs1.x + vs1.y) + (vs1.z + vs1.w);
    float s2  = (vs2.x + vs2.y) + (vs2.z + vs2.w);
    float sx  = (vsx.x + vsx.y) + (vsx.z + vsx.w);
    float ssv = (vss.x + vss.y) + (vss.z + vss.w);
    float ssx = (vssx.x + vssx.y) + (vssx.z + vssx.w);
    float ssl = (vssl.x + vssl.y) + (vssl.z + vssl.w);

#pragma unroll
    for (int off = 16; off; off >>= 1) {
        s1  += __shfl_down_sync(full, s1,  off);
        s2  += __shfl_down_sync(full, s2,  off);
        sx  += __shfl_down_sync(full, sx,  off);
        ssv += __shfl_down_sync(full, ssv, off);
        ssx += __shfl_down_sync(full, ssx, off);
        ssl += __shfl_down_sync(full, ssl, off);
    }

    __shared__ float sm[6][8];
    if (lane == 0) {
        sm[0][wid] = s1;  sm[1][wid] = s2;  sm[2][wid] = sx;
        sm[3][wid] = ssv; sm[4][wid] = ssx; sm[5][wid] = ssl;
    }
    __syncthreads();

    if (tid == 0) {
        s1 = 0.f; s2 = 0.f; sx = 0.f; ssv = 0.f; ssx = 0.f; ssl = 0.f;
#pragma unroll
        for (int w = 0; w < 8; w++) {
            s1 += sm[0][w]; s2 += sm[1][w]; sx += sm[2][w];
            ssv += sm[3][w]; ssx += sm[4][w]; ssl += sm[5][w];
        }
        float logZ1 = __logf(s1);
        float logZ2 = __logf(s2);

        int   b   = r & (BATCH - 1);
        int   lab = labels[b];
        float xl  = logits[(size_t)r * NC + lab];
        float ce  = logZ1 - 0.9f * xl - 0.1f * sx * (1.f / (float)NC);

        float l0 = adv[2 * r], l1 = adv[2 * r + 1];
        float mm = fmaxf(l0, l1);
        float lse = mm + __logf(__expf(l0 - mm) + __expf(l1 - mm));
        float anll = lse - (mod[b] ? l1 : l0);
        g_ce[r] = ce + 0.1f * anll;

        float kl = ssl * 0.6931471805599453f - ssx * (1.f / 3.f) + logZ2 * ssv;
        g_klw[r] = fminf(kl, 5.0f) * ew[r];
    }
}

// ============================================================
// dist2 + final: 128 blocks, block i = anchor i. Combine K-quarter partial
// dots, distances, batch-hard mining (both halves). Last block reduces.
// ============================================================
__global__ __launch_bounds__(256) void dist2_kernel(
    const int* __restrict__ labels,
    const int* __restrict__ epoch_p,
    float*     __restrict__ out)
{
    __shared__ float wmax[2][4], wmin[2][4];
    __shared__ float fm[4][8];
    __shared__ bool  s_last;

    const int tid = threadIdx.x;
    const int lane = tid & 31, wid = tid >> 5;
    const unsigned full = 0xffffffffu;

    int i = blockIdx.x;                 // anchor 0..127
    int p = i >> 1, a = i & 1;

    int h  = tid >> 7;                  // target half
    int jl = tid & 127;
    int jglob = h * 128 + jl;

    float dot = 0.f;
#pragma unroll
    for (int q = 0; q < 4; q++)
        dot += g_dotp[(((size_t)(p * 2 + h) * 4 + q) * 2 + a) * 128 + jl];

    float sqv = g_n2[i] + g_n2[jglob] - 2.f * dot;
    float dj  = sqrtf(fmaxf(sqv, 0.f) + 1e-12f);

    bool eq  = (labels[i] == labels[jl]);
    bool pos = h ? eq : (eq && (jl != i));
    float apv = pos   ? dj : -1e30f;
    float anv = (!eq) ? dj :  1e30f;
#pragma unroll
    for (int off = 16; off; off >>= 1) {
        apv = fmaxf(apv, __shfl_down_sync(full, apv, off));
        anv = fminf(anv, __shfl_down_sync(full, anv, off));
    }
    if (lane == 0) { wmax[h][wid & 3] = apv; wmin[h][wid & 3] = anv; }
    __syncthreads();

    if ((tid & 127) == 0) {
        float apm = fmaxf(fmaxf(wmax[h][0], wmax[h][1]), fmaxf(wmax[h][2], wmax[h][3]));
        float anm = fminf(fminf(wmin[h][0], wmin[h][1]), fminf(wmin[h][2], wmin[h][3]));
        float dap = (apm > -1e29f) ? apm : 0.f;
        float dan = (anm <  1e29f) ? anm : 1e6f;
        g_tri[h * BATCH + i] = fmaxf(dap - dan + 0.3f, 0.f);
        __threadfence();
    }
    __syncthreads();

    // ---- last-block-done final reduce ----
    if (tid == 0) {
        unsigned v = atomicAdd(&g_cnt, 1u);
        s_last = (v == (unsigned)(gridDim.x - 1));
    }
    __syncthreads();
    if (!s_last) return;
    if (tid == 0) { g_cnt = 0; __threadfence(); }

    float ceA = 0.f, klwA = 0.f, tri0 = 0.f, tri1 = 0.f;
    for (int r = tid; r < ROWS; r += 256) {
        ceA  += g_ce[r];
        klwA += g_klw[r];
    }
    if (tid < BATCH) { tri0 = g_tri[tid]; tri1 = g_tri[BATCH + tid]; }

#pragma unroll
    for (int off = 16; off; off >>= 1) {
        ceA  += __shfl_down_sync(full, ceA,  off);
        klwA += __shfl_down_sync(full, klwA, off);
        tri0 += __shfl_down_sync(full, tri0, off);
        tri1 += __shfl_down_sync(full, tri1, off);
    }
    if (lane == 0) {
        fm[0][wid] = ceA; fm[1][wid] = klwA; fm[2][wid] = tri0; fm[3][wid] = tri1;
    }
    __syncthreads();

    if (tid == 0) {
        float ceT = 0.f, klwT = 0.f, t0 = 0.f, t1 = 0.f;
#pragma unroll
        for (int w = 0; w < 8; w++) {
            ceT += fm[0][w]; klwT += fm[1][w]; t0 += fm[2][w]; t1 += fm[3][w];
        }
        float L_idadv = ceT * (1.f / (float)ROWS);   // includes 0.1*L_adv
        float L_tri   = (t0 + 0.5f * t1) * (1.f / (float)BATCH);
        float L_graph = (epoch_p[0] >= 20) ? klwT * (9.f / (float)ROWS) : 0.f;
        out[0] = L_idadv + L_tri + 0.1f * L_graph;
    }
}

// ============================================================
extern "C" void kernel_launch(void* const* d_in, const int* in_sizes, int n_in,
                              void* d_out, int out_size)
{
    const float* id_logits     = (const float*)d_in[0];
    const float* id_features   = (const float*)d_in[1];
    const float* gray_features = (const float*)d_in[2];
    const float* soft_labels   = (const float*)d_in[3];
    const float* entropy_w     = (const float*)d_in[4];
    const float* adv_logits    = (const float*)d_in[5];
    const int*   labels        = (const int*)d_in[6];
    const int*   mod_labels    = (const int*)d_in[7];
    const int*   epoch         = (const int*)d_in[8];

    prep_kernel<<<256, 256>>>(id_features, gray_features);
    dist1_kernel<<<512, 256>>>();
    row_kernel<<<ROWS, 256>>>(id_logits, soft_labels, entropy_w, labels,
                              adv_logits, mod_labels);
    dist2_kernel<<<BATCH, 256>>>(labels, epoch, (float*)d_out);
}

// round 9
// speedup vs baseline: 1.3406x; 1.0262x over previous
#include <cuda_runtime.h>
#include <cuda_bf16.h>

#define NC 50000
#define BATCH 128
#define ROWS 768                 // 6 parts * 128
#define DIM 1536                 // 6 * 256
#define N4 12500                 // float4 per row
#define KE 192                   // K per dist1 block (DIM/8)
#define NDIST2 128
#define NMEGA (NDIST2 + ROWS)    // 896

// ---------------- device scratch (no cudaMalloc allowed) ----------------
__device__ float g_ce[ROWS];            // ce + 0.1*adv_nll per row
__device__ float g_klw[ROWS];
__device__ float g_tri[2 * BATCH];
__device__ float g_F[BATCH * DIM];      // normalized feat rows, fp32
__device__ __align__(16) __nv_bfloat16 g_TtB[DIM * 256]; // transposed targets
__device__ float g_n2[256];
__device__ float g_dotp[64 * 2 * 8 * 2 * 128]; // [pair][half][eighth][anchor][jl]
__device__ unsigned g_cnt;              // last-block counter (self-resetting)

__device__ __forceinline__ float ex2(float v) {
    float r;
    asm("ex2.approx.ftz.f32 %0, %1;" : "=f"(r) : "f"(v));
    return r;
}

// ============================================================
// prep: normalize concatenated part features; fp32 rows + bf16 transpose.
// ============================================================
__global__ __launch_bounds__(256) void prep_kernel(
    const float* __restrict__ idf, const float* __restrict__ gf)
{
    const int tid = threadIdx.x;
    const int lane = tid & 31, wid = tid >> 5;
    const unsigned full = 0xffffffffu;

    int j = blockIdx.x;                 // 0..255
    const float* src = (j < BATCH) ? idf : gf;
    int b = j & (BATCH - 1);

    float v[6];
    float sq = 0.f;
#pragma unroll
    for (int p = 0; p < 6; p++) {
        float x = src[(size_t)(p * BATCH + b) * 256 + tid];
        v[p] = x;
        sq = fmaf(x, x, sq);
    }
#pragma unroll
    for (int off = 16; off; off >>= 1) sq += __shfl_down_sync(full, sq, off);
    __shared__ float wsum[8];
    if (lane == 0) wsum[wid] = sq;
    __syncthreads();
    float tot = 0.f;
#pragma unroll
    for (int w = 0; w < 8; w++) tot += wsum[w];
    float rn = rsqrtf(tot);
#pragma unroll
    for (int p = 0; p < 6; p++) {
        int d = p * 256 + tid;
        float nv = v[p] * rn;
        g_TtB[(size_t)d * 256 + j] = __float2bfloat16_rn(nv);
        if (j < BATCH) g_F[(size_t)b * DIM + d] = nv;
    }
    if (tid == 0) g_n2[j] = tot * rn * rn;
}

// ============================================================
// dist1: 1024 blocks = (64 pairs) x (2 halves) x (8 K-eighths).
// Each block: partial dots of 2 anchors vs 128 targets over 192 k.
// ~7 blocks/SM -> latency fully hidden.
// ============================================================
__global__ __launch_bounds__(256) void dist1_kernel()
{
    __shared__ float As[2][KE];          // 1.5 KB
    __shared__ float red[8][2][128];     // 8 KB

    const int tid = threadIdx.x;
    const int lane = tid & 31, wid = tid >> 5;

    int p = blockIdx.x >> 4;
    int h = (blockIdx.x >> 3) & 1;
    int q = blockIdx.x & 7;
    int i0 = p * 2;
    int k0 = q * KE;

    // load anchor segments: 2 x 192 floats
    {
        int idx = tid;                  // 0..255
        if (idx < 2 * KE) {
            int a  = idx >= KE;
            int kk = a ? idx - KE : idx;
            As[a][kk] = g_F[(size_t)(i0 + a) * DIM + k0 + kk];
        }
        int idx2 = tid + 256;
        if (idx2 < 2 * KE) {
            As[1][idx2 - KE] = g_F[(size_t)(i0 + 1) * DIM + k0 + idx2 - KE];
        }
    }
    __syncthreads();

    // slice = warp (24 k each); lane -> 4 targets (uint2 of bf16)
    const uint2* T2 = (const uint2*)g_TtB;
    const int ks = wid * 24;
    const uint2* Tp = T2 + (size_t)(k0 + ks) * 64 + (h * 32 + lane);

    float c00 = 0.f, c01 = 0.f, c02 = 0.f, c03 = 0.f;
    float c10 = 0.f, c11 = 0.f, c12 = 0.f, c13 = 0.f;

#pragma unroll 1
    for (int kk = 0; kk < 24; kk += 8) {
        uint2 t[8];
#pragma unroll
        for (int u = 0; u < 8; u++) t[u] = Tp[(size_t)(kk + u) * 64];
#pragma unroll
        for (int u = 0; u < 8; u++) {
            float f0 = __uint_as_float(t[u].x << 16);
            float f1 = __uint_as_float(t[u].x & 0xffff0000u);
            float f2 = __uint_as_float(t[u].y << 16);
            float f3 = __uint_as_float(t[u].y & 0xffff0000u);
            float A0 = As[0][ks + kk + u], A1 = As[1][ks + kk + u];
            c00 = fmaf(A0, f0, c00); c01 = fmaf(A0, f1, c01);
            c02 = fmaf(A0, f2, c02); c03 = fmaf(A0, f3, c03);
            c10 = fmaf(A1, f0, c10); c11 = fmaf(A1, f1, c11);
            c12 = fmaf(A1, f2, c12); c13 = fmaf(A1, f3, c13);
        }
    }
    ((float4*)red[wid][0])[lane] = make_float4(c00, c01, c02, c03);
    ((float4*)red[wid][1])[lane] = make_float4(c10, c11, c12, c13);
    __syncthreads();

    int a  = tid >> 7;
    int jl = tid & 127;
    float dot = 0.f;
#pragma unroll
    for (int sl = 0; sl < 8; sl++) dot += red[sl][a][jl];
    g_dotp[(((size_t)(p * 2 + h) * 8 + q) * 2 + a) * 128 + jl] = dot;
}

// ============================================================
// rowmega: bid 0..127 = dist2 path (combine partials, distances, mining);
//          bid 128..895 = row path (dual-temp softmax stats, HBM-bound).
// dist1 completed before this launch, so dist2 blocks are valid in wave 1.
// Last finished block performs the final scalar reduce.
// ============================================================
__global__ __launch_bounds__(256, 3) void rowmega_kernel(
    const float* __restrict__ logits, const float* __restrict__ soft,
    const float* __restrict__ ew,     const int*   __restrict__ labels,
    const float* __restrict__ adv,    const int*   __restrict__ mod,
    const int*   __restrict__ epoch_p, float* __restrict__ out)
{
    __shared__ float sm[6][8];
    __shared__ float wmax[2][4], wmin[2][4];
    __shared__ bool  s_last;

    const int tid = threadIdx.x;
    const int lane = tid & 31, wid = tid >> 5;
    const unsigned full = 0xffffffffu;

    if (blockIdx.x < NDIST2) {
        // ==================== dist2 path ====================
        int i = blockIdx.x;             // anchor 0..127
        int p = i >> 1, a = i & 1;

        int h  = tid >> 7;              // target half
        int jl = tid & 127;
        int jglob = h * 128 + jl;

        float dot = 0.f;
#pragma unroll
        for (int q = 0; q < 8; q++)
            dot += g_dotp[(((size_t)(p * 2 + h) * 8 + q) * 2 + a) * 128 + jl];

        float sqv = g_n2[i] + g_n2[jglob] - 2.f * dot;
        float dj  = sqrtf(fmaxf(sqv, 0.f) + 1e-12f);

        bool eq  = (labels[i] == labels[jl]);
        bool pos = h ? eq : (eq && (jl != i));
        float apv = pos   ? dj : -1e30f;
        float anv = (!eq) ? dj :  1e30f;
#pragma unroll
        for (int off = 16; off; off >>= 1) {
            apv = fmaxf(apv, __shfl_down_sync(full, apv, off));
            anv = fminf(anv, __shfl_down_sync(full, anv, off));
        }
        if (lane == 0) { wmax[h][wid & 3] = apv; wmin[h][wid & 3] = anv; }
        __syncthreads();

        if ((tid & 127) == 0) {
            float apm = fmaxf(fmaxf(wmax[h][0], wmax[h][1]),
                              fmaxf(wmax[h][2], wmax[h][3]));
            float anm = fminf(fminf(wmin[h][0], wmin[h][1]),
                              fminf(wmin[h][2], wmin[h][3]));
            float dap = (apm > -1e29f) ? apm : 0.f;
            float dan = (anm <  1e29f) ? anm : 1e6f;
            g_tri[h * BATCH + i] = fmaxf(dap - dan + 0.3f, 0.f);
            __threadfence();
        }
    } else {
        // ==================== row path ====================
        const int r = blockIdx.x - NDIST2;
        const float4* lg4 = (const float4*)(logits + (size_t)r * NC);
        const float4* sf4 = (const float4*)(soft   + (size_t)r * NC);
        const float C = 0.48089834696298783f;   // log2(e)/3

        float4 vs1 = {0,0,0,0}, vs2 = {0,0,0,0}, vsx = {0,0,0,0};
        float4 vss = {0,0,0,0}, vssx = {0,0,0,0}, vssl = {0,0,0,0};

#define ACC(xx, sv_, L)                                               \
    {   float x = xx, sv = sv_;                                       \
        vsx.L += x;  vss.L += sv;                                     \
        vssx.L = fmaf(sv, x, vssx.L);                                 \
        vssl.L = fmaf(sv, __log2f(fmaxf(sv, 1e-38f)), vssl.L);        \
        float e = ex2(x * C);                                         \
        vs2.L += e;                                                   \
        vs1.L = fmaf(e * e, e, vs1.L); }
#define LANE4(x4, t4) ACC(x4.x, t4.x, x) ACC(x4.y, t4.y, y) \
                      ACC(x4.z, t4.z, z) ACC(x4.w, t4.w, w)

        int i = tid;
        for (; i + 768 < N4; i += 1024) {
            float4 x0 = __ldcs(lg4 + i);
            float4 x1 = __ldcs(lg4 + i + 256);
            float4 x2 = __ldcs(lg4 + i + 512);
            float4 x3 = __ldcs(lg4 + i + 768);
            float4 t0 = __ldcs(sf4 + i);
            float4 t1 = __ldcs(sf4 + i + 256);
            float4 t2 = __ldcs(sf4 + i + 512);
            float4 t3 = __ldcs(sf4 + i + 768);
            LANE4(x0, t0) LANE4(x1, t1) LANE4(x2, t2) LANE4(x3, t3)
        }
        for (; i < N4; i += 256) {
            float4 x0 = __ldcs(lg4 + i);
            float4 t0 = __ldcs(sf4 + i);
            LANE4(x0, t0)
        }
#undef LANE4
#undef ACC

        float s1  = (vs1.x + vs1.y) + (vs1.z + vs1.w);
        float s2  = (vs2.x + vs2.y) + (vs2.z + vs2.w);
        float sx  = (vsx.x + vsx.y) + (vsx.z + vsx.w);
        float ssv = (vss.x + vss.y) + (vss.z + vss.w);
        float ssx = (vssx.x + vssx.y) + (vssx.z + vssx.w);
        float ssl = (vssl.x + vssl.y) + (vssl.z + vssl.w);

#pragma unroll
        for (int off = 16; off; off >>= 1) {
            s1  += __shfl_down_sync(full, s1,  off);
            s2  += __shfl_down_sync(full, s2,  off);
            sx  += __shfl_down_sync(full, sx,  off);
            ssv += __shfl_down_sync(full, ssv, off);
            ssx += __shfl_down_sync(full, ssx, off);
            ssl += __shfl_down_sync(full, ssl, off);
        }

        if (lane == 0) {
            sm[0][wid] = s1;  sm[1][wid] = s2;  sm[2][wid] = sx;
            sm[3][wid] = ssv; sm[4][wid] = ssx; sm[5][wid] = ssl;
        }
        __syncthreads();

        if (tid == 0) {
            s1 = 0.f; s2 = 0.f; sx = 0.f; ssv = 0.f; ssx = 0.f; ssl = 0.f;
#pragma unroll
            for (int w = 0; w < 8; w++) {
                s1 += sm[0][w]; s2 += sm[1][w]; sx += sm[2][w];
                ssv += sm[3][w]; ssx += sm[4][w]; ssl += sm[5][w];
            }
            float logZ1 = __logf(s1);
            float logZ2 = __logf(s2);

            int   b   = r & (BATCH - 1);
            int   lab = labels[b];
            float xl  = logits[(size_t)r * NC + lab];
            float ce  = logZ1 - 0.9f * xl - 0.1f * sx * (1.f / (float)NC);

            float l0 = adv[2 * r], l1 = adv[2 * r + 1];
            float mm = fmaxf(l0, l1);
            float lse = mm + __logf(__expf(l0 - mm) + __expf(l1 - mm));
            float anll = lse - (mod[b] ? l1 : l0);
            g_ce[r] = ce + 0.1f * anll;

            float kl = ssl * 0.6931471805599453f - ssx * (1.f / 3.f) + logZ2 * ssv;
            g_klw[r] = fminf(kl, 5.0f) * ew[r];
            __threadfence();
        }
    }

    // ================= last-block-done final reduce =================
    __syncthreads();
    if (tid == 0) {
        unsigned v = atomicAdd(&g_cnt, 1u);
        s_last = (v == (unsigned)(NMEGA - 1));
    }
    __syncthreads();
    if (!s_last) return;
    if (tid == 0) { g_cnt = 0; __threadfence(); }

    float ceA = 0.f, klwA = 0.f, tri0 = 0.f, tri1 = 0.f;
    for (int r = tid; r < ROWS; r += 256) {
        ceA  += g_ce[r];
        klwA += g_klw[r];
    }
    if (tid < BATCH) { tri0 = g_tri[tid]; tri1 = g_tri[BATCH + tid]; }

#pragma unroll
    for (int off = 16; off; off >>= 1) {
        ceA  += __shfl_down_sync(full, ceA,  off);
        klwA += __shfl_down_sync(full, klwA, off);
        tri0 += __shfl_down_sync(full, tri0, off);
        tri1 += __shfl_down_sync(full, tri1, off);
    }
    __shared__ float fm[4][8];
    if (lane == 0) {
        fm[0][wid] = ceA; fm[1][wid] = klwA; fm[2][wid] = tri0; fm[3][wid] = tri1;
    }
    __syncthreads();

    if (tid == 0) {
        float ceT = 0.f, klwT = 0.f, t0 = 0.f, t1 = 0.f;
#pragma unroll
        for (int w = 0; w < 8; w++) {
            ceT += fm[0][w]; klwT += fm[1][w]; t0 += fm[2][w]; t1 += fm[3][w];
        }
        float L_idadv = ceT * (1.f / (float)ROWS);   // includes 0.1*L_adv
        float L_tri   = (t0 + 0.5f * t1) * (1.f / (float)BATCH);
        float L_graph = (epoch_p[0] >= 20) ? klwT * (9.f / (float)ROWS) : 0.f;
        out[0] = L_idadv + L_tri + 0.1f * L_graph;
    }
}

// ============================================================
extern "C" void kernel_launch(void* const* d_in, const int* in_sizes, int n_in,
                              void* d_out, int out_size)
{
    const float* id_logits     = (const float*)d_in[0];
    const float* id_features   = (const float*)d_in[1];
    const float* gray_features = (const float*)d_in[2];
    const float* soft_labels   = (const float*)d_in[3];
    const float* entropy_w     = (const float*)d_in[4];
    const float* adv_logits    = (const float*)d_in[5];
    const int*   labels        = (const int*)d_in[6];
    const int*   mod_labels    = (const int*)d_in[7];
    const int*   epoch         = (const int*)d_in[8];

    prep_kernel<<<256, 256>>>(id_features, gray_features);
    dist1_kernel<<<1024, 256>>>();
    rowmega_kernel<<<NMEGA, 256>>>(id_logits, soft_labels, entropy_w, labels,
                                   adv_logits, mod_labels,
                                   epoch, (float*)d_out);
}